// round 13
// baseline (speedup 1.0000x reference)
#include <cuda_runtime.h>
#include <cstdint>

// Problem constants
#define DDIM 4096
#define NEXP 64
#define NTOK 16384          // B*S
#define BM   64             // rows per CTA (2 CTAs/SM)
#define KC   32             // K per stage
#define NSTAGE (DDIM / KC)  // 128
#define NCTA (NTOK / BM)    // 256
#define S36  36             // smem row stride (36 mod 32 = 4 -> conflict-free frags)

// Output layout (tuple flattened to float32 in reference order)
#define IDX_OFF   0
#define SC_OFF    32768
#define PB_OFF    65536
#define Z_OFF     1114112
#define IMP_OFF   1114113
#define LOAD_OFF  1114177

// Dynamic smem (float offsets): xh[2]@0/2304, xl[2]@4608/6912,
// wh[2]@9216/11520, wl[2]@13824/16128. Total 18432 floats = 72KB.
// After mainloop: ls[64][65]=4160 @0, st[129] @4160 (reuse).
#define XH(b) ((b) * 2304)
#define XL(b) (4608 + (b) * 2304)
#define WH(b) (9216 + (b) * 2304)
#define WL(b) (13824 + (b) * 2304)
#define DSM_BYTES (18432 * 4)

// Per-CTA partial stats: [0..63] importance, [64..127] counts, [128] z^2
__device__ float g_part[NCTA][129];
__device__ unsigned int g_ctr = 0;   // self-resetting via atomicInc wrap

// ---------- helpers ----------
__device__ __forceinline__ void tf32pair(float v, uint32_t& h, uint32_t& l) {
    asm("cvt.rna.tf32.f32 %0, %1;" : "=r"(h) : "f"(v));
    float r = v - __uint_as_float(h);
    asm("cvt.rna.tf32.f32 %0, %1;" : "=r"(l) : "f"(r));
}
__device__ __forceinline__ void mma8(float* d,
                                     uint32_t a0, uint32_t a1, uint32_t a2, uint32_t a3,
                                     uint32_t b0, uint32_t b1) {
    asm volatile(
        "mma.sync.aligned.m16n8k8.row.col.f32.tf32.tf32.f32 "
        "{%0,%1,%2,%3},{%4,%5,%6,%7},{%8,%9},{%0,%1,%2,%3};"
        : "+f"(d[0]), "+f"(d[1]), "+f"(d[2]), "+f"(d[3])
        : "r"(a0), "r"(a1), "r"(a2), "r"(a3), "r"(b0), "r"(b1));
}
__device__ __forceinline__ void ldsm4(uint32_t& r0, uint32_t& r1,
                                      uint32_t& r2, uint32_t& r3, uint32_t addr) {
    asm volatile("ldmatrix.sync.aligned.m8n8.x4.shared.b16 {%0,%1,%2,%3}, [%4];"
                 : "=r"(r0), "=r"(r1), "=r"(r2), "=r"(r3) : "r"(addr));
}

// ---------- single fused kernel ----------
// grid = 256 CTAs (one per 64-token tile), block = 256 threads (8 warps),
// 2 CTAs/SM — cross-CTA overlap hides the per-stage convert/barrier phases.
// Warp tile: 16 rows x 32 experts; A frags via ldmatrix.x4; 3-product tf32.
extern "C" __global__ void __launch_bounds__(256, 2)
router_kernel(const float* __restrict__ x, const float* __restrict__ W,
              float* __restrict__ out) {
    extern __shared__ __align__(16) float dsm[];

    const int tid  = threadIdx.x;
    const int warp = tid >> 5;
    const int lane = tid & 31;
    const int g = lane >> 2;      // group row
    const int t = lane & 3;       // thread-in-group
    const int rowbase = blockIdx.x * BM;
    const float* xg0 = x + (size_t)rowbase * DDIM;

    const int wrow  = (warp >> 1) * 16;   // 4 row blocks of 16
    const int cbase = (warp & 1) * 32;    // 2 expert halves

    uint32_t dsm_a;
    asm("{ .reg .u64 t0; cvta.to.shared.u64 t0, %1; cvt.u32.u64 %0, t0; }"
        : "=r"(dsm_a) : "l"(dsm));

    // ldmatrix lane address (element offset within a tile buffer)
    const int arow = wrow + (lane & 7) + ((lane >> 3) & 1) * 8;
    const int aoff = arow * S36 + ((lane >> 4) & 1) * 4;

    // ---- register-prefetch double-buffered loader ----
    // x: 512 quads/stage -> 2 per thread; w: 512 quads -> 2 per thread.
    float4 xr[2], wr[2];
    #pragma unroll
    for (int i = 0; i < 2; i++) {
        int c = tid + 256 * i, r = c >> 3, q = c & 7;
        xr[i] = *(const float4*)(xg0 + (size_t)r * DDIM + (q << 2));
    }
    #pragma unroll
    for (int i = 0; i < 2; i++) {
        int c = tid + 256 * i, r = c >> 3, q = c & 7;
        wr[i] = *(const float4*)(W + (size_t)r * DDIM + (q << 2));
    }

    float acc[4][4];   // [n tile][frag]
    #pragma unroll
    for (int nt = 0; nt < 4; nt++)
        #pragma unroll
        for (int e = 0; e < 4; e++) acc[nt][e] = 0.0f;

    #pragma unroll 1
    for (int s = 0; s < NSTAGE; s++) {
        const int b = s & 1;

        // prefetch next stage
        float4 xn[2], wn[2];
        if (s + 1 < NSTAGE) {
            const float* xg = xg0 + (s + 1) * KC;
            const float* wg = W + (s + 1) * KC;
            #pragma unroll
            for (int i = 0; i < 2; i++) {
                int c = tid + 256 * i, r = c >> 3, q = c & 7;
                xn[i] = *(const float4*)(xg + (size_t)r * DDIM + (q << 2));
            }
            #pragma unroll
            for (int i = 0; i < 2; i++) {
                int c = tid + 256 * i, r = c >> 3, q = c & 7;
                wn[i] = *(const float4*)(wg + (size_t)r * DDIM + (q << 2));
            }
        }

        // convert current stage fp32 -> (tf32 hi, tf32 lo), store to smem
        #pragma unroll
        for (int i = 0; i < 2; i++) {
            int c = tid + 256 * i, r = c >> 3, q = c & 7;
            uint4 h, l;
            tf32pair(xr[i].x, h.x, l.x);
            tf32pair(xr[i].y, h.y, l.y);
            tf32pair(xr[i].z, h.z, l.z);
            tf32pair(xr[i].w, h.w, l.w);
            int off = r * S36 + (q << 2);
            *(uint4*)(dsm + XH(b) + off) = h;
            *(uint4*)(dsm + XL(b) + off) = l;
        }
        #pragma unroll
        for (int i = 0; i < 2; i++) {
            int c = tid + 256 * i, r = c >> 3, q = c & 7;
            uint4 h, l;
            tf32pair(wr[i].x, h.x, l.x);
            tf32pair(wr[i].y, h.y, l.y);
            tf32pair(wr[i].z, h.z, l.z);
            tf32pair(wr[i].w, h.w, l.w);
            int off = r * S36 + (q << 2);
            *(uint4*)(dsm + WH(b) + off) = h;
            *(uint4*)(dsm + WL(b) + off) = l;
        }
        __syncthreads();

        // ---- MMA phase: 4 k8-steps, 4 n-tiles, 3 products ----
        const uint32_t ah_base = dsm_a + (uint32_t)(XH(b) + aoff) * 4;
        const uint32_t al_base = dsm_a + (uint32_t)(XL(b) + aoff) * 4;
        const uint32_t* wh = (const uint32_t*)(dsm + WH(b)) + (cbase + g) * S36 + t;
        const uint32_t* wl = (const uint32_t*)(dsm + WL(b)) + (cbase + g) * S36 + t;

        #pragma unroll
        for (int kq = 0; kq < 4; kq++) {
            const int k0 = kq * 8;
            uint32_t ah[4], al[4];
            ldsm4(ah[0], ah[1], ah[2], ah[3], ah_base + (uint32_t)k0 * 4);
            ldsm4(al[0], al[1], al[2], al[3], al_base + (uint32_t)k0 * 4);
            #pragma unroll
            for (int nt = 0; nt < 4; nt++) {
                const uint32_t* wph = wh + nt * 8 * S36;
                const uint32_t* wpl = wl + nt * 8 * S36;
                uint32_t bh0 = wph[k0], bh1 = wph[k0 + 4];
                uint32_t bl0 = wpl[k0], bl1 = wpl[k0 + 4];
                mma8(acc[nt], al[0], al[1], al[2], al[3], bh0, bh1);  // lh
                mma8(acc[nt], ah[0], ah[1], ah[2], ah[3], bl0, bl1);  // hl
                mma8(acc[nt], ah[0], ah[1], ah[2], ah[3], bh0, bh1);  // hh
            }
        }

        #pragma unroll
        for (int i = 0; i < 2; i++) xr[i] = xn[i];
        #pragma unroll
        for (int i = 0; i < 2; i++) wr[i] = wn[i];
    }
    __syncthreads();   // last stage's MMAs done before smem reuse

    // ---- epilogue: logits -> smem ls[64][65] ----
    float* ls = dsm;
    float* st = dsm + 4160;
    #pragma unroll
    for (int nt = 0; nt < 4; nt++) {
        const int c0 = cbase + nt * 8 + 2 * t;
        const int r0 = wrow + g;
        ls[r0 * 65 + c0]           = acc[nt][0];
        ls[r0 * 65 + c0 + 1]       = acc[nt][1];
        ls[(r0 + 8) * 65 + c0]     = acc[nt][2];
        ls[(r0 + 8) * 65 + c0 + 1] = acc[nt][3];
    }
    if (tid < 129) st[tid] = 0.0f;
    __syncthreads();

    // ---- router: 8 warps, 8 rows per warp ----
    const float NEG_INF = __int_as_float(0xff800000u);
    float imp0 = 0.f, imp1 = 0.f, cnt0 = 0.f, cnt1 = 0.f, z2 = 0.f;
    float* probs_out = out + PB_OFF;

    #pragma unroll 2
    for (int it = 0; it < 8; it++) {
        const int rl = warp * 8 + it;
        const int row = rowbase + rl;
        const float va = ls[rl * 65 + lane];
        const float vb = ls[rl * 65 + lane + 32];

        float bv; int bi;
        if (va >= vb) { bv = va; bi = lane; } else { bv = vb; bi = lane + 32; }
        #pragma unroll
        for (int off = 16; off; off >>= 1) {
            float ov = __shfl_xor_sync(0xffffffffu, bv, off);
            int   oi = __shfl_xor_sync(0xffffffffu, bi, off);
            if (ov > bv || (ov == bv && oi < bi)) { bv = ov; bi = oi; }
        }
        float va2 = (lane == bi)      ? NEG_INF : va;
        float vb2 = (lane + 32 == bi) ? NEG_INF : vb;
        float sv; int si;
        if (va2 >= vb2) { sv = va2; si = lane; } else { sv = vb2; si = lane + 32; }
        #pragma unroll
        for (int off = 16; off; off >>= 1) {
            float ov = __shfl_xor_sync(0xffffffffu, sv, off);
            int   oi = __shfl_xor_sync(0xffffffffu, si, off);
            if (ov > sv || (ov == sv && oi < si)) { sv = ov; si = oi; }
        }

        const float ea = __expf(va - bv);
        const float eb = __expf(vb - bv);
        float ssum = ea + eb;
        #pragma unroll
        for (int off = 16; off; off >>= 1)
            ssum += __shfl_xor_sync(0xffffffffu, ssum, off);
        const float inv = 1.0f / ssum;
        const float pa = ea * inv, pb = eb * inv;

        probs_out[(size_t)row * 64 + lane]      = pa;
        probs_out[(size_t)row * 64 + lane + 32] = pb;

        imp0 += pa; imp1 += pb;
        cnt0 += (bi == lane      ? 1.f : 0.f) + (si == lane      ? 1.f : 0.f);
        cnt1 += (bi == lane + 32 ? 1.f : 0.f) + (si == lane + 32 ? 1.f : 0.f);

        if (lane == 0) {
            const float z = bv + __logf(ssum);
            z2 += z * z;
            out[IDX_OFF + row * 2]     = (float)bi;
            out[IDX_OFF + row * 2 + 1] = (float)si;
            const float e2 = __expf(sv - bv);
            const float dn = 1.0f / (1.0f + e2);
            out[SC_OFF + row * 2]     = dn;
            out[SC_OFF + row * 2 + 1] = e2 * dn;
        }
    }

    // ---- CTA-level stats reduce in smem, then one row of g_part ----
    atomicAdd(&st[lane],      imp0);
    atomicAdd(&st[lane + 32], imp1);
    atomicAdd(&st[64 + lane], cnt0);
    atomicAdd(&st[96 + lane], cnt1);
    if (lane == 0) atomicAdd(&st[128], z2);
    __syncthreads();

    if (tid < 129) g_part[blockIdx.x][tid] = st[tid];

    // ---- last-CTA finalize (self-resetting counter) ----
    __shared__ unsigned int s_last;
    __threadfence();
    __syncthreads();
    if (tid == 0) {
        unsigned int old = atomicInc(&g_ctr, NCTA - 1);
        s_last = (old == NCTA - 1) ? 1u : 0u;
    }
    __syncthreads();
    if (s_last && tid < 129) {
        __threadfence();
        float ssum = 0.f;
        #pragma unroll 1
        for (int c = 0; c < NCTA; c++) ssum += g_part[c][tid];
        if (tid < 64)       out[IMP_OFF + tid]         = ssum * (1.0f / 16384.0f);
        else if (tid < 128) out[LOAD_OFF + (tid - 64)] = ssum * (1.0f / 32768.0f);
        else                out[Z_OFF]                 = ssum * (1.0f / 16384.0f);
    }
}

extern "C" void kernel_launch(void* const* d_in, const int* in_sizes, int n_in,
                              void* d_out, int out_size) {
    const float* x = (const float*)d_in[0];   // [4,4096,4096] f32
    const float* W = (const float*)d_in[1];   // [64,4096] f32
    float* out = (float*)d_out;
    (void)in_sizes; (void)n_in; (void)out_size;
    cudaFuncSetAttribute(router_kernel, cudaFuncAttributeMaxDynamicSharedMemorySize,
                         DSM_BYTES);
    router_kernel<<<NCTA, 256, DSM_BYTES>>>(x, W, out);
}

// round 14
// speedup vs baseline: 1.1762x; 1.1762x over previous
#include <cuda_runtime.h>
#include <cstdint>

// Problem constants
#define DDIM 4096
#define NEXP 64
#define NTOK 16384          // B*S
#define BM   128
#define KC   32             // K per stage
#define NSTAGE (DDIM / KC)  // 128
#define NCTA (NTOK / BM)    // 128
#define S36  36             // smem row stride (36 mod 32 = 4 -> conflict-free frags)

// Output layout (tuple flattened to float32 in reference order)
#define IDX_OFF   0
#define SC_OFF    32768
#define PB_OFF    65536
#define Z_OFF     1114112
#define IMP_OFF   1114113
#define LOAD_OFF  1114177

// Dynamic smem (float offsets): xh[2]@0/4608, xl[2]@9216/13824,
// wh[2]@18432/20736, wl[2]@23040/25344. Total 27648 floats = 108KB.
// After mainloop: ls[128][65] @0, st[129] @8320 (reuse).
#define XH(b) ((b) * 4608)
#define XL(b) (9216 + (b) * 4608)
#define WH(b) (18432 + (b) * 2304)
#define WL(b) (23040 + (b) * 2304)
#define DSM_BYTES (27648 * 4)

// Per-CTA partial stats + W hi/lo split (precomputed once per launch)
__device__ float g_part[NCTA][129];
__device__ unsigned int g_ctr = 0;   // self-resetting via atomicInc wrap
__device__ float g_whi[NEXP * DDIM];
__device__ float g_wlo[NEXP * DDIM];

// ---------- helpers ----------
__device__ __forceinline__ void tf32pair(float v, uint32_t& h, uint32_t& l) {
    asm("cvt.rna.tf32.f32 %0, %1;" : "=r"(h) : "f"(v));
    float r = v - __uint_as_float(h);
    asm("cvt.rna.tf32.f32 %0, %1;" : "=r"(l) : "f"(r));
}
__device__ __forceinline__ void mma8(float* d,
                                     uint32_t a0, uint32_t a1, uint32_t a2, uint32_t a3,
                                     uint32_t b0, uint32_t b1) {
    asm volatile(
        "mma.sync.aligned.m16n8k8.row.col.f32.tf32.tf32.f32 "
        "{%0,%1,%2,%3},{%4,%5,%6,%7},{%8,%9},{%0,%1,%2,%3};"
        : "+f"(d[0]), "+f"(d[1]), "+f"(d[2]), "+f"(d[3])
        : "r"(a0), "r"(a1), "r"(a2), "r"(a3), "r"(b0), "r"(b1));
}
__device__ __forceinline__ void ldsm4(uint32_t& r0, uint32_t& r1,
                                      uint32_t& r2, uint32_t& r3, uint32_t addr) {
    asm volatile("ldmatrix.sync.aligned.m8n8.x4.shared.b16 {%0,%1,%2,%3}, [%4];"
                 : "=r"(r0), "=r"(r1), "=r"(r2), "=r"(r3) : "r"(addr));
}
__device__ __forceinline__ void cp16(uint32_t dst, const void* src) {
    asm volatile("cp.async.cg.shared.global [%0], [%1], 16;" :: "r"(dst), "l"(src));
}
__device__ __forceinline__ void cp_commit() {
    asm volatile("cp.async.commit_group;" ::: "memory");
}
template <int N> __device__ __forceinline__ void cp_wait() {
    asm volatile("cp.async.wait_group %0;" :: "n"(N) : "memory");
}

// ---------- W split prologue kernel ----------
extern "C" __global__ void wsplit_kernel(const float* __restrict__ W) {
    int i = blockIdx.x * blockDim.x + threadIdx.x;   // 262144 = NEXP*DDIM
    uint32_t h, l;
    tf32pair(W[i], h, l);
    g_whi[i] = __uint_as_float(h);
    g_wlo[i] = __uint_as_float(l);
}

// ---------- fused GEMM+router kernel ----------
// grid = 128 CTAs, block = 256 threads (8 warps, 2/SMSP).
// Warp tile: 32 rows x 32 experts. A and B frags via ldmatrix.x4;
// W hi/lo streamed by cp.async from precomputed global split.
extern "C" __global__ void __launch_bounds__(256, 1)
router_kernel(const float* __restrict__ x, float* __restrict__ out) {
    extern __shared__ __align__(16) float dsm[];

    const int tid  = threadIdx.x;
    const int warp = tid >> 5;
    const int lane = tid & 31;
    const int g = lane >> 2;      // group row
    const int t = lane & 3;       // thread-in-group
    const int rowbase = blockIdx.x * BM;
    const float* xg0 = x + (size_t)rowbase * DDIM;

    const int wrow  = (warp >> 1) * 32;   // 4 row blocks of 32
    const int cbase = (warp & 1) * 32;    // 2 expert halves

    uint32_t dsm_a;
    asm("{ .reg .u64 t0; cvta.to.shared.u64 t0, %1; cvt.u32.u64 %0, t0; }"
        : "=r"(dsm_a) : "l"(dsm));

    // ldmatrix lane addresses (element offsets within tile buffers)
    const int aoff = (wrow + (lane & 7) + ((lane >> 3) & 1) * 8) * S36
                   + ((lane >> 4) & 1) * 4;
    const int boff = (cbase + (lane & 7) + ((lane >> 3) & 1) * 8) * S36
                   + ((lane >> 4) & 1) * 4;

    // W cp.async slots: 512 quads each for hi/lo -> 2+2 per thread
    const int wr_r = tid >> 3, wr_q = tid & 7;           // c = tid (quads 0..255)
    const int wr_r2 = (tid + 256) >> 3, wr_q2 = (tid + 256) & 7;
    const uint32_t wdst1 = (uint32_t)(wr_r  * S36 + wr_q  * 4) * 4;
    const uint32_t wdst2 = (uint32_t)(wr_r2 * S36 + wr_q2 * 4) * 4;

    auto cp_w_stage = [&](int s, int b) {
        const float* hsrc = g_whi + (size_t)0 + s * KC;
        const float* lsrc = g_wlo + (size_t)0 + s * KC;
        uint32_t wh_a = dsm_a + (uint32_t)WH(b) * 4;
        uint32_t wl_a = dsm_a + (uint32_t)WL(b) * 4;
        cp16(wh_a + wdst1, hsrc + (size_t)wr_r  * DDIM + wr_q  * 4);
        cp16(wh_a + wdst2, hsrc + (size_t)wr_r2 * DDIM + wr_q2 * 4);
        cp16(wl_a + wdst1, lsrc + (size_t)wr_r  * DDIM + wr_q  * 4);
        cp16(wl_a + wdst2, lsrc + (size_t)wr_r2 * DDIM + wr_q2 * 4);
        cp_commit();
    };

    // ---- prologue: x regs + W cp for stage 0 ----
    float4 xr[4];
    #pragma unroll
    for (int i = 0; i < 4; i++) {
        int c = tid + 256 * i, r = c >> 3, q = c & 7;
        xr[i] = *(const float4*)(xg0 + (size_t)r * DDIM + (q << 2));
    }
    cp_w_stage(0, 0);

    float acc[2][4][4];   // [row block][n tile][frag]
    #pragma unroll
    for (int rb = 0; rb < 2; rb++)
        #pragma unroll
        for (int nt = 0; nt < 4; nt++)
            #pragma unroll
            for (int e = 0; e < 4; e++) acc[rb][nt][e] = 0.0f;

    #pragma unroll 1
    for (int s = 0; s < NSTAGE; s++) {
        const int b = s & 1;

        // prefetch next-stage x into registers
        float4 xn[4];
        if (s + 1 < NSTAGE) {
            const float* xg = xg0 + (s + 1) * KC;
            #pragma unroll
            for (int i = 0; i < 4; i++) {
                int c = tid + 256 * i, r = c >> 3, q = c & 7;
                xn[i] = *(const float4*)(xg + (size_t)r * DDIM + (q << 2));
            }
        }

        // convert current-stage x fp32 -> (tf32 hi, lo), store to smem buf b
        #pragma unroll
        for (int i = 0; i < 4; i++) {
            int c = tid + 256 * i, r = c >> 3, q = c & 7;
            uint4 h, l;
            tf32pair(xr[i].x, h.x, l.x);
            tf32pair(xr[i].y, h.y, l.y);
            tf32pair(xr[i].z, h.z, l.z);
            tf32pair(xr[i].w, h.w, l.w);
            int off = r * S36 + (q << 2);
            *(uint4*)(dsm + XH(b) + off) = h;
            *(uint4*)(dsm + XL(b) + off) = l;
        }

        cp_wait<0>();     // this stage's W tiles landed
        __syncthreads();  // everyone's x stores + W visible; s-1 MMA readers done

        // issue W cp for stage s+1 into buf b^1 (safe: post-barrier)
        if (s + 1 < NSTAGE) cp_w_stage(s + 1, b ^ 1);

        // ---- MMA phase: 4 k8-steps, 2 row blocks, 4 n-tiles, 3 products ----
        const uint32_t ah_base = dsm_a + (uint32_t)(XH(b) + aoff) * 4;
        const uint32_t al_base = dsm_a + (uint32_t)(XL(b) + aoff) * 4;
        const uint32_t bh_base = dsm_a + (uint32_t)(WH(b) + boff) * 4;
        const uint32_t bl_base = dsm_a + (uint32_t)(WL(b) + boff) * 4;

        #pragma unroll
        for (int kq = 0; kq < 4; kq++) {
            const int k0 = kq * 8;
            uint32_t ah[2][4], al[2][4];
            #pragma unroll
            for (int rb = 0; rb < 2; rb++) {
                ldsm4(ah[rb][0], ah[rb][1], ah[rb][2], ah[rb][3],
                      ah_base + (uint32_t)(rb * 16 * S36 + k0) * 4);
                ldsm4(al[rb][0], al[rb][1], al[rb][2], al[rb][3],
                      al_base + (uint32_t)(rb * 16 * S36 + k0) * 4);
            }
            // B frags: one ldsm4 covers 2 n-tiles (16 experts)
            uint32_t bh[2][4], bl[2][4];
            ldsm4(bh[0][0], bh[0][1], bh[0][2], bh[0][3], bh_base + (uint32_t)k0 * 4);
            ldsm4(bh[1][0], bh[1][1], bh[1][2], bh[1][3],
                  bh_base + (uint32_t)(16 * S36 + k0) * 4);
            ldsm4(bl[0][0], bl[0][1], bl[0][2], bl[0][3], bl_base + (uint32_t)k0 * 4);
            ldsm4(bl[1][0], bl[1][1], bl[1][2], bl[1][3],
                  bl_base + (uint32_t)(16 * S36 + k0) * 4);
            #pragma unroll
            for (int nt = 0; nt < 4; nt++) {
                const int blk = nt >> 1, idx = nt & 1;
                uint32_t bh0 = bh[blk][idx], bh1 = bh[blk][idx + 2];
                uint32_t bl0 = bl[blk][idx], bl1 = bl[blk][idx + 2];
                #pragma unroll
                for (int rb = 0; rb < 2; rb++) {
                    mma8(acc[rb][nt], al[rb][0], al[rb][1], al[rb][2], al[rb][3],
                         bh0, bh1);                                       // lh
                    mma8(acc[rb][nt], ah[rb][0], ah[rb][1], ah[rb][2], ah[rb][3],
                         bl0, bl1);                                       // hl
                    mma8(acc[rb][nt], ah[rb][0], ah[rb][1], ah[rb][2], ah[rb][3],
                         bh0, bh1);                                       // hh
                }
            }
        }

        #pragma unroll
        for (int i = 0; i < 4; i++) xr[i] = xn[i];
    }
    __syncthreads();   // last stage's MMAs done before smem reuse

    // ---- epilogue: logits -> smem ls[128][65] ----
    float* ls = dsm;
    float* st = dsm + 8320;
    #pragma unroll
    for (int rb = 0; rb < 2; rb++)
        #pragma unroll
        for (int nt = 0; nt < 4; nt++) {
            const int c0 = cbase + nt * 8 + 2 * t;
            const int r0 = wrow + rb * 16 + g;
            ls[r0 * 65 + c0]           = acc[rb][nt][0];
            ls[r0 * 65 + c0 + 1]       = acc[rb][nt][1];
            ls[(r0 + 8) * 65 + c0]     = acc[rb][nt][2];
            ls[(r0 + 8) * 65 + c0 + 1] = acc[rb][nt][3];
        }
    if (tid < 129) st[tid] = 0.0f;
    __syncthreads();

    // ---- router: 8 warps, 16 rows per warp (proven code) ----
    const float NEG_INF = __int_as_float(0xff800000u);
    float imp0 = 0.f, imp1 = 0.f, cnt0 = 0.f, cnt1 = 0.f, z2 = 0.f;
    float* probs_out = out + PB_OFF;

    #pragma unroll 2
    for (int it = 0; it < 16; it++) {
        const int rl = warp * 16 + it;
        const int row = rowbase + rl;
        const float va = ls[rl * 65 + lane];
        const float vb = ls[rl * 65 + lane + 32];

        float bv; int bi;
        if (va >= vb) { bv = va; bi = lane; } else { bv = vb; bi = lane + 32; }
        #pragma unroll
        for (int off = 16; off; off >>= 1) {
            float ov = __shfl_xor_sync(0xffffffffu, bv, off);
            int   oi = __shfl_xor_sync(0xffffffffu, bi, off);
            if (ov > bv || (ov == bv && oi < bi)) { bv = ov; bi = oi; }
        }
        float va2 = (lane == bi)      ? NEG_INF : va;
        float vb2 = (lane + 32 == bi) ? NEG_INF : vb;
        float sv; int si;
        if (va2 >= vb2) { sv = va2; si = lane; } else { sv = vb2; si = lane + 32; }
        #pragma unroll
        for (int off = 16; off; off >>= 1) {
            float ov = __shfl_xor_sync(0xffffffffu, sv, off);
            int   oi = __shfl_xor_sync(0xffffffffu, si, off);
            if (ov > sv || (ov == sv && oi < si)) { sv = ov; si = oi; }
        }

        const float ea = __expf(va - bv);
        const float eb = __expf(vb - bv);
        float ssum = ea + eb;
        #pragma unroll
        for (int off = 16; off; off >>= 1)
            ssum += __shfl_xor_sync(0xffffffffu, ssum, off);
        const float inv = 1.0f / ssum;
        const float pa = ea * inv, pb = eb * inv;

        probs_out[(size_t)row * 64 + lane]      = pa;
        probs_out[(size_t)row * 64 + lane + 32] = pb;

        imp0 += pa; imp1 += pb;
        cnt0 += (bi == lane      ? 1.f : 0.f) + (si == lane      ? 1.f : 0.f);
        cnt1 += (bi == lane + 32 ? 1.f : 0.f) + (si == lane + 32 ? 1.f : 0.f);

        if (lane == 0) {
            const float z = bv + __logf(ssum);
            z2 += z * z;
            out[IDX_OFF + row * 2]     = (float)bi;
            out[IDX_OFF + row * 2 + 1] = (float)si;
            const float e2 = __expf(sv - bv);
            const float dn = 1.0f / (1.0f + e2);
            out[SC_OFF + row * 2]     = dn;
            out[SC_OFF + row * 2 + 1] = e2 * dn;
        }
    }

    // ---- CTA-level stats reduce in smem, then one row of g_part ----
    atomicAdd(&st[lane],      imp0);
    atomicAdd(&st[lane + 32], imp1);
    atomicAdd(&st[64 + lane], cnt0);
    atomicAdd(&st[96 + lane], cnt1);
    if (lane == 0) atomicAdd(&st[128], z2);
    __syncthreads();

    if (tid < 129) g_part[blockIdx.x][tid] = st[tid];

    // ---- last-CTA finalize (self-resetting counter) ----
    __shared__ unsigned int s_last;
    __threadfence();
    __syncthreads();
    if (tid == 0) {
        unsigned int old = atomicInc(&g_ctr, NCTA - 1);
        s_last = (old == NCTA - 1) ? 1u : 0u;
    }
    __syncthreads();
    if (s_last && tid < 129) {
        __threadfence();
        float ssum = 0.f;
        #pragma unroll 1
        for (int c = 0; c < NCTA; c++) ssum += g_part[c][tid];
        if (tid < 64)       out[IMP_OFF + tid]         = ssum * (1.0f / 16384.0f);
        else if (tid < 128) out[LOAD_OFF + (tid - 64)] = ssum * (1.0f / 32768.0f);
        else                out[Z_OFF]                 = ssum * (1.0f / 16384.0f);
    }
}

extern "C" void kernel_launch(void* const* d_in, const int* in_sizes, int n_in,
                              void* d_out, int out_size) {
    const float* x = (const float*)d_in[0];   // [4,4096,4096] f32
    const float* W = (const float*)d_in[1];   // [64,4096] f32
    float* out = (float*)d_out;
    (void)in_sizes; (void)n_in; (void)out_size;
    wsplit_kernel<<<(NEXP * DDIM) / 256, 256>>>(W);
    cudaFuncSetAttribute(router_kernel, cudaFuncAttributeMaxDynamicSharedMemorySize,
                         DSM_BYTES);
    router_kernel<<<NCTA, 256, DSM_BYTES>>>(x, out);
}

// round 15
// speedup vs baseline: 1.2894x; 1.0963x over previous
#include <cuda_runtime.h>
#include <cstdint>

// Problem constants
#define DDIM 4096
#define NEXP 64
#define NTOK 16384          // B*S
#define BM   128
#define KC   32             // K per stage
#define NSTAGE (DDIM / KC)  // 128
#define NCTA (NTOK / BM)    // 128
#define S36  36             // smem row stride (36 mod 32 = 4 -> conflict-free frags)

// Output layout (tuple flattened to float32 in reference order)
#define IDX_OFF   0
#define SC_OFF    32768
#define PB_OFF    65536
#define Z_OFF     1114112
#define IMP_OFF   1114113
#define LOAD_OFF  1114177

// Dynamic smem (float offsets): xh[2]@0/4608, xl[2]@9216/13824,
// wh[2]@18432/20736, wl[2]@23040/25344. Total 27648 floats = 108KB.
// After mainloop: ls[128][65] @0, st[129] @8320 (reuse).
#define XH(b) ((b) * 4608)
#define XL(b) (9216 + (b) * 4608)
#define WH(b) (18432 + (b) * 2304)
#define WL(b) (23040 + (b) * 2304)
#define DSM_BYTES (27648 * 4)

// Per-CTA partial stats: [0..63] importance, [64..127] counts, [128] z^2
__device__ float g_part[NCTA][129];
__device__ unsigned int g_ctr = 0;   // self-resetting via atomicInc wrap

// ---------- helpers ----------
__device__ __forceinline__ void tf32pair(float v, uint32_t& h, uint32_t& l) {
    asm("cvt.rna.tf32.f32 %0, %1;" : "=r"(h) : "f"(v));
    float r = v - __uint_as_float(h);
    asm("cvt.rna.tf32.f32 %0, %1;" : "=r"(l) : "f"(r));
}
__device__ __forceinline__ void mma8(float* d,
                                     uint32_t a0, uint32_t a1, uint32_t a2, uint32_t a3,
                                     uint32_t b0, uint32_t b1) {
    asm volatile(
        "mma.sync.aligned.m16n8k8.row.col.f32.tf32.tf32.f32 "
        "{%0,%1,%2,%3},{%4,%5,%6,%7},{%8,%9},{%0,%1,%2,%3};"
        : "+f"(d[0]), "+f"(d[1]), "+f"(d[2]), "+f"(d[3])
        : "r"(a0), "r"(a1), "r"(a2), "r"(a3), "r"(b0), "r"(b1));
}
__device__ __forceinline__ void ldsm4(uint32_t& r0, uint32_t& r1,
                                      uint32_t& r2, uint32_t& r3, uint32_t addr) {
    asm volatile("ldmatrix.sync.aligned.m8n8.x4.shared.b16 {%0,%1,%2,%3}, [%4];"
                 : "=r"(r0), "=r"(r1), "=r"(r2), "=r"(r3) : "r"(addr));
}

// ---------- single fused kernel (R11 structure + B via ldsm4) ----------
// grid = 128 CTAs, block = 256 threads (8 warps, 2/SMSP).
// Warp tile: 32 rows x 32 experts. A and B frags via ldmatrix.x4;
// 3-product tf32 emulation (hh + hl + lh).
extern "C" __global__ void __launch_bounds__(256, 1)
router_kernel(const float* __restrict__ x, const float* __restrict__ W,
              float* __restrict__ out) {
    extern __shared__ __align__(16) float dsm[];

    const int tid  = threadIdx.x;
    const int warp = tid >> 5;
    const int lane = tid & 31;
    const int g = lane >> 2;      // group row
    const int t = lane & 3;       // thread-in-group
    const int rowbase = blockIdx.x * BM;
    const float* xg0 = x + (size_t)rowbase * DDIM;

    const int wrow  = (warp >> 1) * 32;   // 4 row blocks of 32
    const int cbase = (warp & 1) * 32;    // 2 expert halves

    uint32_t dsm_a;
    asm("{ .reg .u64 t0; cvta.to.shared.u64 t0, %1; cvt.u32.u64 %0, t0; }"
        : "=r"(dsm_a) : "l"(dsm));

    // ldmatrix lane addresses (element offsets within tile buffers)
    const int aoff = (wrow + (lane & 7) + ((lane >> 3) & 1) * 8) * S36
                   + ((lane >> 4) & 1) * 4;
    const int boff = (cbase + (lane & 7) + ((lane >> 3) & 1) * 8) * S36
                   + ((lane >> 4) & 1) * 4;

    // ---- register-prefetch double-buffered loader (R11 scheme) ----
    float4 xr[4], wr[2];
    #pragma unroll
    for (int i = 0; i < 4; i++) {
        int c = tid + 256 * i, r = c >> 3, q = c & 7;
        xr[i] = *(const float4*)(xg0 + (size_t)r * DDIM + (q << 2));
    }
    #pragma unroll
    for (int i = 0; i < 2; i++) {
        int c = tid + 256 * i, r = c >> 3, q = c & 7;
        wr[i] = *(const float4*)(W + (size_t)r * DDIM + (q << 2));
    }

    float acc[2][4][4];   // [row block][n tile][frag]
    #pragma unroll
    for (int rb = 0; rb < 2; rb++)
        #pragma unroll
        for (int nt = 0; nt < 4; nt++)
            #pragma unroll
            for (int e = 0; e < 4; e++) acc[rb][nt][e] = 0.0f;

    #pragma unroll 1
    for (int s = 0; s < NSTAGE; s++) {
        const int b = s & 1;

        // prefetch next stage
        float4 xn[4], wn[2];
        if (s + 1 < NSTAGE) {
            const float* xg = xg0 + (s + 1) * KC;
            const float* wg = W + (s + 1) * KC;
            #pragma unroll
            for (int i = 0; i < 4; i++) {
                int c = tid + 256 * i, r = c >> 3, q = c & 7;
                xn[i] = *(const float4*)(xg + (size_t)r * DDIM + (q << 2));
            }
            #pragma unroll
            for (int i = 0; i < 2; i++) {
                int c = tid + 256 * i, r = c >> 3, q = c & 7;
                wn[i] = *(const float4*)(wg + (size_t)r * DDIM + (q << 2));
            }
        }

        // convert current stage fp32 -> (tf32 hi, tf32 lo), store to smem
        #pragma unroll
        for (int i = 0; i < 4; i++) {
            int c = tid + 256 * i, r = c >> 3, q = c & 7;
            uint4 h, l;
            tf32pair(xr[i].x, h.x, l.x);
            tf32pair(xr[i].y, h.y, l.y);
            tf32pair(xr[i].z, h.z, l.z);
            tf32pair(xr[i].w, h.w, l.w);
            int off = r * S36 + (q << 2);
            *(uint4*)(dsm + XH(b) + off) = h;
            *(uint4*)(dsm + XL(b) + off) = l;
        }
        #pragma unroll
        for (int i = 0; i < 2; i++) {
            int c = tid + 256 * i, r = c >> 3, q = c & 7;
            uint4 h, l;
            tf32pair(wr[i].x, h.x, l.x);
            tf32pair(wr[i].y, h.y, l.y);
            tf32pair(wr[i].z, h.z, l.z);
            tf32pair(wr[i].w, h.w, l.w);
            int off = r * S36 + (q << 2);
            *(uint4*)(dsm + WH(b) + off) = h;
            *(uint4*)(dsm + WL(b) + off) = l;
        }
        __syncthreads();

        // ---- MMA phase: 4 k8-steps, 2 row blocks, 4 n-tiles, 3 products ----
        const uint32_t ah_base = dsm_a + (uint32_t)(XH(b) + aoff) * 4;
        const uint32_t al_base = dsm_a + (uint32_t)(XL(b) + aoff) * 4;
        const uint32_t bh_base = dsm_a + (uint32_t)(WH(b) + boff) * 4;
        const uint32_t bl_base = dsm_a + (uint32_t)(WL(b) + boff) * 4;

        #pragma unroll
        for (int kq = 0; kq < 4; kq++) {
            const int k0 = kq * 8;
            uint32_t ah[2][4], al[2][4];
            #pragma unroll
            for (int rb = 0; rb < 2; rb++) {
                ldsm4(ah[rb][0], ah[rb][1], ah[rb][2], ah[rb][3],
                      ah_base + (uint32_t)(rb * 16 * S36 + k0) * 4);
                ldsm4(al[rb][0], al[rb][1], al[rb][2], al[rb][3],
                      al_base + (uint32_t)(rb * 16 * S36 + k0) * 4);
            }
            // B frags: one ldsm4 covers 2 n-tiles (16 experts) — validated in R14
            uint32_t bh[2][4], bl[2][4];
            ldsm4(bh[0][0], bh[0][1], bh[0][2], bh[0][3], bh_base + (uint32_t)k0 * 4);
            ldsm4(bh[1][0], bh[1][1], bh[1][2], bh[1][3],
                  bh_base + (uint32_t)(16 * S36 + k0) * 4);
            ldsm4(bl[0][0], bl[0][1], bl[0][2], bl[0][3], bl_base + (uint32_t)k0 * 4);
            ldsm4(bl[1][0], bl[1][1], bl[1][2], bl[1][3],
                  bl_base + (uint32_t)(16 * S36 + k0) * 4);
            #pragma unroll
            for (int nt = 0; nt < 4; nt++) {
                const int blk = nt >> 1, idx = nt & 1;
                uint32_t bh0 = bh[blk][idx], bh1 = bh[blk][idx + 2];
                uint32_t bl0 = bl[blk][idx], bl1 = bl[blk][idx + 2];
                #pragma unroll
                for (int rb = 0; rb < 2; rb++) {
                    mma8(acc[rb][nt], al[rb][0], al[rb][1], al[rb][2], al[rb][3],
                         bh0, bh1);                                       // lh
                    mma8(acc[rb][nt], ah[rb][0], ah[rb][1], ah[rb][2], ah[rb][3],
                         bl0, bl1);                                       // hl
                    mma8(acc[rb][nt], ah[rb][0], ah[rb][1], ah[rb][2], ah[rb][3],
                         bh0, bh1);                                       // hh
                }
            }
        }

        #pragma unroll
        for (int i = 0; i < 4; i++) xr[i] = xn[i];
        #pragma unroll
        for (int i = 0; i < 2; i++) wr[i] = wn[i];
    }
    __syncthreads();   // last stage's MMAs done before smem reuse

    // ---- epilogue: logits -> smem ls[128][65] ----
    float* ls = dsm;
    float* st = dsm + 8320;
    #pragma unroll
    for (int rb = 0; rb < 2; rb++)
        #pragma unroll
        for (int nt = 0; nt < 4; nt++) {
            const int c0 = cbase + nt * 8 + 2 * t;
            const int r0 = wrow + rb * 16 + g;
            ls[r0 * 65 + c0]           = acc[rb][nt][0];
            ls[r0 * 65 + c0 + 1]       = acc[rb][nt][1];
            ls[(r0 + 8) * 65 + c0]     = acc[rb][nt][2];
            ls[(r0 + 8) * 65 + c0 + 1] = acc[rb][nt][3];
        }
    if (tid < 129) st[tid] = 0.0f;
    __syncthreads();

    // ---- router: 8 warps, 16 rows per warp (proven code) ----
    const float NEG_INF = __int_as_float(0xff800000u);
    float imp0 = 0.f, imp1 = 0.f, cnt0 = 0.f, cnt1 = 0.f, z2 = 0.f;
    float* probs_out = out + PB_OFF;

    #pragma unroll 2
    for (int it = 0; it < 16; it++) {
        const int rl = warp * 16 + it;
        const int row = rowbase + rl;
        const float va = ls[rl * 65 + lane];
        const float vb = ls[rl * 65 + lane + 32];

        float bv; int bi;
        if (va >= vb) { bv = va; bi = lane; } else { bv = vb; bi = lane + 32; }
        #pragma unroll
        for (int off = 16; off; off >>= 1) {
            float ov = __shfl_xor_sync(0xffffffffu, bv, off);
            int   oi = __shfl_xor_sync(0xffffffffu, bi, off);
            if (ov > bv || (ov == bv && oi < bi)) { bv = ov; bi = oi; }
        }
        float va2 = (lane == bi)      ? NEG_INF : va;
        float vb2 = (lane + 32 == bi) ? NEG_INF : vb;
        float sv; int si;
        if (va2 >= vb2) { sv = va2; si = lane; } else { sv = vb2; si = lane + 32; }
        #pragma unroll
        for (int off = 16; off; off >>= 1) {
            float ov = __shfl_xor_sync(0xffffffffu, sv, off);
            int   oi = __shfl_xor_sync(0xffffffffu, si, off);
            if (ov > sv || (ov == sv && oi < si)) { sv = ov; si = oi; }
        }

        const float ea = __expf(va - bv);
        const float eb = __expf(vb - bv);
        float ssum = ea + eb;
        #pragma unroll
        for (int off = 16; off; off >>= 1)
            ssum += __shfl_xor_sync(0xffffffffu, ssum, off);
        const float inv = 1.0f / ssum;
        const float pa = ea * inv, pb = eb * inv;

        probs_out[(size_t)row * 64 + lane]      = pa;
        probs_out[(size_t)row * 64 + lane + 32] = pb;

        imp0 += pa; imp1 += pb;
        cnt0 += (bi == lane      ? 1.f : 0.f) + (si == lane      ? 1.f : 0.f);
        cnt1 += (bi == lane + 32 ? 1.f : 0.f) + (si == lane + 32 ? 1.f : 0.f);

        if (lane == 0) {
            const float z = bv + __logf(ssum);
            z2 += z * z;
            out[IDX_OFF + row * 2]     = (float)bi;
            out[IDX_OFF + row * 2 + 1] = (float)si;
            const float e2 = __expf(sv - bv);
            const float dn = 1.0f / (1.0f + e2);
            out[SC_OFF + row * 2]     = dn;
            out[SC_OFF + row * 2 + 1] = e2 * dn;
        }
    }

    // ---- CTA-level stats reduce in smem, then one row of g_part ----
    atomicAdd(&st[lane],      imp0);
    atomicAdd(&st[lane + 32], imp1);
    atomicAdd(&st[64 + lane], cnt0);
    atomicAdd(&st[96 + lane], cnt1);
    if (lane == 0) atomicAdd(&st[128], z2);
    __syncthreads();

    if (tid < 129) g_part[blockIdx.x][tid] = st[tid];

    // ---- last-CTA finalize (self-resetting counter) ----
    __shared__ unsigned int s_last;
    __threadfence();
    __syncthreads();
    if (tid == 0) {
        unsigned int old = atomicInc(&g_ctr, NCTA - 1);
        s_last = (old == NCTA - 1) ? 1u : 0u;
    }
    __syncthreads();
    if (s_last && tid < 129) {
        __threadfence();
        float ssum = 0.f;
        #pragma unroll 1
        for (int c = 0; c < NCTA; c++) ssum += g_part[c][tid];
        if (tid < 64)       out[IMP_OFF + tid]         = ssum * (1.0f / 16384.0f);
        else if (tid < 128) out[LOAD_OFF + (tid - 64)] = ssum * (1.0f / 32768.0f);
        else                out[Z_OFF]                 = ssum * (1.0f / 16384.0f);
    }
}

extern "C" void kernel_launch(void* const* d_in, const int* in_sizes, int n_in,
                              void* d_out, int out_size) {
    const float* x = (const float*)d_in[0];   // [4,4096,4096] f32
    const float* W = (const float*)d_in[1];   // [64,4096] f32
    float* out = (float*)d_out;
    (void)in_sizes; (void)n_in; (void)out_size;
    cudaFuncSetAttribute(router_kernel, cudaFuncAttributeMaxDynamicSharedMemorySize,
                         DSM_BYTES);
    router_kernel<<<NCTA, 256, DSM_BYTES>>>(x, W, out);
}

// round 16
// speedup vs baseline: 2.1199x; 1.6441x over previous
#include <cuda_runtime.h>
#include <cstdint>

// Problem constants
#define DDIM 4096
#define NEXP 64
#define NTOK 16384          // B*S
#define BM   128
#define KC   32             // K per stage
#define NSTAGE (DDIM / KC)  // 128
#define NCTA (NTOK / BM)    // 128
#define S36  36             // smem row stride (36 mod 32 = 4 -> conflict-free frags)

// Output layout (tuple flattened to float32 in reference order)
#define IDX_OFF   0
#define SC_OFF    32768
#define PB_OFF    65536
#define Z_OFF     1114112
#define IMP_OFF   1114113
#define LOAD_OFF  1114177

// Dynamic smem (float offsets): xh[2]@0/4608, xl[2]@9216/13824,
// wh[2]@18432/20736, wl[2]@23040/25344. Total 27648 floats = 108KB.
// After mainloop: ls[128][65] @0, st[129] @8320 (reuse).
#define XH(b) ((b) * 4608)
#define XL(b) (9216 + (b) * 4608)
#define WH(b) (18432 + (b) * 2304)
#define WL(b) (23040 + (b) * 2304)
#define DSM_BYTES (27648 * 4)

// Per-CTA partial stats: [0..63] importance, [64..127] counts, [128] z^2
__device__ float g_part[NCTA][129];
__device__ unsigned int g_ctr = 0;   // self-resetting via atomicInc wrap

// ---------- helpers ----------
__device__ __forceinline__ void tf32pair(float v, uint32_t& h, uint32_t& l) {
    asm("cvt.rna.tf32.f32 %0, %1;" : "=r"(h) : "f"(v));
    float r = v - __uint_as_float(h);
    asm("cvt.rna.tf32.f32 %0, %1;" : "=r"(l) : "f"(r));
}
__device__ __forceinline__ void mma8(float* d,
                                     uint32_t a0, uint32_t a1, uint32_t a2, uint32_t a3,
                                     uint32_t b0, uint32_t b1) {
    asm volatile(
        "mma.sync.aligned.m16n8k8.row.col.f32.tf32.tf32.f32 "
        "{%0,%1,%2,%3},{%4,%5,%6,%7},{%8,%9},{%0,%1,%2,%3};"
        : "+f"(d[0]), "+f"(d[1]), "+f"(d[2]), "+f"(d[3])
        : "r"(a0), "r"(a1), "r"(a2), "r"(a3), "r"(b0), "r"(b1));
}
__device__ __forceinline__ void ldsm4(uint32_t& r0, uint32_t& r1,
                                      uint32_t& r2, uint32_t& r3, uint32_t addr) {
    asm volatile("ldmatrix.sync.aligned.m8n8.x4.shared.b16 {%0,%1,%2,%3}, [%4];"
                 : "=r"(r0), "=r"(r1), "=r"(r2), "=r"(r3) : "r"(addr));
}

// ---------- single fused kernel (R11 structure, product-major MMA order) ----------
// grid = 128 CTAs, block = 256 threads (8 warps, 2/SMSP).
// Warp tile: 32 rows x 32 experts. A frags via ldmatrix.x4, B via scalar LDS;
// 3-product tf32 emulation issued PRODUCT-MAJOR: 8 independent acc chains
// between consecutive same-accumulator MMAs (covers HMMA latency).
extern "C" __global__ void __launch_bounds__(256, 1)
router_kernel(const float* __restrict__ x, const float* __restrict__ W,
              float* __restrict__ out) {
    extern __shared__ __align__(16) float dsm[];

    const int tid  = threadIdx.x;
    const int warp = tid >> 5;
    const int lane = tid & 31;
    const int g = lane >> 2;      // group row
    const int t = lane & 3;       // thread-in-group
    const int rowbase = blockIdx.x * BM;
    const float* xg0 = x + (size_t)rowbase * DDIM;

    const int wrow  = (warp >> 1) * 32;   // 4 row blocks of 32
    const int cbase = (warp & 1) * 32;    // 2 expert halves

    uint32_t dsm_a;
    asm("{ .reg .u64 t0; cvta.to.shared.u64 t0, %1; cvt.u32.u64 %0, t0; }"
        : "=r"(dsm_a) : "l"(dsm));

    // ldmatrix lane address for A (element offset within tile buffers)
    const int aoff = (wrow + (lane & 7) + ((lane >> 3) & 1) * 8) * S36
                   + ((lane >> 4) & 1) * 4;

    // ---- register-prefetch double-buffered loader (R11 scheme) ----
    float4 xr[4], wr[2];
    #pragma unroll
    for (int i = 0; i < 4; i++) {
        int c = tid + 256 * i, r = c >> 3, q = c & 7;
        xr[i] = *(const float4*)(xg0 + (size_t)r * DDIM + (q << 2));
    }
    #pragma unroll
    for (int i = 0; i < 2; i++) {
        int c = tid + 256 * i, r = c >> 3, q = c & 7;
        wr[i] = *(const float4*)(W + (size_t)r * DDIM + (q << 2));
    }

    float acc[2][4][4];   // [row block][n tile][frag]
    #pragma unroll
    for (int rb = 0; rb < 2; rb++)
        #pragma unroll
        for (int nt = 0; nt < 4; nt++)
            #pragma unroll
            for (int e = 0; e < 4; e++) acc[rb][nt][e] = 0.0f;

    #pragma unroll 1
    for (int s = 0; s < NSTAGE; s++) {
        const int b = s & 1;

        // prefetch next stage
        float4 xn[4], wn[2];
        if (s + 1 < NSTAGE) {
            const float* xg = xg0 + (s + 1) * KC;
            const float* wg = W + (s + 1) * KC;
            #pragma unroll
            for (int i = 0; i < 4; i++) {
                int c = tid + 256 * i, r = c >> 3, q = c & 7;
                xn[i] = *(const float4*)(xg + (size_t)r * DDIM + (q << 2));
            }
            #pragma unroll
            for (int i = 0; i < 2; i++) {
                int c = tid + 256 * i, r = c >> 3, q = c & 7;
                wn[i] = *(const float4*)(wg + (size_t)r * DDIM + (q << 2));
            }
        }

        // convert current stage fp32 -> (tf32 hi, tf32 lo), store to smem
        #pragma unroll
        for (int i = 0; i < 4; i++) {
            int c = tid + 256 * i, r = c >> 3, q = c & 7;
            uint4 h, l;
            tf32pair(xr[i].x, h.x, l.x);
            tf32pair(xr[i].y, h.y, l.y);
            tf32pair(xr[i].z, h.z, l.z);
            tf32pair(xr[i].w, h.w, l.w);
            int off = r * S36 + (q << 2);
            *(uint4*)(dsm + XH(b) + off) = h;
            *(uint4*)(dsm + XL(b) + off) = l;
        }
        #pragma unroll
        for (int i = 0; i < 2; i++) {
            int c = tid + 256 * i, r = c >> 3, q = c & 7;
            uint4 h, l;
            tf32pair(wr[i].x, h.x, l.x);
            tf32pair(wr[i].y, h.y, l.y);
            tf32pair(wr[i].z, h.z, l.z);
            tf32pair(wr[i].w, h.w, l.w);
            int off = r * S36 + (q << 2);
            *(uint4*)(dsm + WH(b) + off) = h;
            *(uint4*)(dsm + WL(b) + off) = l;
        }
        __syncthreads();

        // ---- MMA phase: 4 k8-steps; PRODUCT-MAJOR issue order ----
        const uint32_t ah_base = dsm_a + (uint32_t)(XH(b) + aoff) * 4;
        const uint32_t al_base = dsm_a + (uint32_t)(XL(b) + aoff) * 4;
        const uint32_t* wh = (const uint32_t*)(dsm + WH(b)) + (cbase + g) * S36 + t;
        const uint32_t* wl = (const uint32_t*)(dsm + WL(b)) + (cbase + g) * S36 + t;

        #pragma unroll
        for (int kq = 0; kq < 4; kq++) {
            const int k0 = kq * 8;
            uint32_t ah[2][4], al[2][4];
            #pragma unroll
            for (int rb = 0; rb < 2; rb++) {
                ldsm4(ah[rb][0], ah[rb][1], ah[rb][2], ah[rb][3],
                      ah_base + (uint32_t)(rb * 16 * S36 + k0) * 4);
                ldsm4(al[rb][0], al[rb][1], al[rb][2], al[rb][3],
                      al_base + (uint32_t)(rb * 16 * S36 + k0) * 4);
            }
            // hoist all B frags (scalar LDS, R11-style)
            uint32_t bh0[4], bh1[4], bl0[4], bl1[4];
            #pragma unroll
            for (int nt = 0; nt < 4; nt++) {
                const uint32_t* wph = wh + nt * 8 * S36;
                const uint32_t* wpl = wl + nt * 8 * S36;
                bh0[nt] = wph[k0]; bh1[nt] = wph[k0 + 4];
                bl0[nt] = wpl[k0]; bl1[nt] = wpl[k0 + 4];
            }
            // product-major: 8 independent chains between same-acc issues
            #pragma unroll
            for (int nt = 0; nt < 4; nt++)
                #pragma unroll
                for (int rb = 0; rb < 2; rb++)
                    mma8(acc[rb][nt], al[rb][0], al[rb][1], al[rb][2], al[rb][3],
                         bh0[nt], bh1[nt]);                               // lh
            #pragma unroll
            for (int nt = 0; nt < 4; nt++)
                #pragma unroll
                for (int rb = 0; rb < 2; rb++)
                    mma8(acc[rb][nt], ah[rb][0], ah[rb][1], ah[rb][2], ah[rb][3],
                         bl0[nt], bl1[nt]);                               // hl
            #pragma unroll
            for (int nt = 0; nt < 4; nt++)
                #pragma unroll
                for (int rb = 0; rb < 2; rb++)
                    mma8(acc[rb][nt], ah[rb][0], ah[rb][1], ah[rb][2], ah[rb][3],
                         bh0[nt], bh1[nt]);                               // hh
        }

        #pragma unroll
        for (int i = 0; i < 4; i++) xr[i] = xn[i];
        #pragma unroll
        for (int i = 0; i < 2; i++) wr[i] = wn[i];
    }
    __syncthreads();   // last stage's MMAs done before smem reuse

    // ---- epilogue: logits -> smem ls[128][65] ----
    float* ls = dsm;
    float* st = dsm + 8320;
    #pragma unroll
    for (int rb = 0; rb < 2; rb++)
        #pragma unroll
        for (int nt = 0; nt < 4; nt++) {
            const int c0 = cbase + nt * 8 + 2 * t;
            const int r0 = wrow + rb * 16 + g;
            ls[r0 * 65 + c0]           = acc[rb][nt][0];
            ls[r0 * 65 + c0 + 1]       = acc[rb][nt][1];
            ls[(r0 + 8) * 65 + c0]     = acc[rb][nt][2];
            ls[(r0 + 8) * 65 + c0 + 1] = acc[rb][nt][3];
        }
    if (tid < 129) st[tid] = 0.0f;
    __syncthreads();

    // ---- router: 8 warps, 16 rows per warp (proven code) ----
    const float NEG_INF = __int_as_float(0xff800000u);
    float imp0 = 0.f, imp1 = 0.f, cnt0 = 0.f, cnt1 = 0.f, z2 = 0.f;
    float* probs_out = out + PB_OFF;

    #pragma unroll 2
    for (int it = 0; it < 16; it++) {
        const int rl = warp * 16 + it;
        const int row = rowbase + rl;
        const float va = ls[rl * 65 + lane];
        const float vb = ls[rl * 65 + lane + 32];

        float bv; int bi;
        if (va >= vb) { bv = va; bi = lane; } else { bv = vb; bi = lane + 32; }
        #pragma unroll
        for (int off = 16; off; off >>= 1) {
            float ov = __shfl_xor_sync(0xffffffffu, bv, off);
            int   oi = __shfl_xor_sync(0xffffffffu, bi, off);
            if (ov > bv || (ov == bv && oi < bi)) { bv = ov; bi = oi; }
        }
        float va2 = (lane == bi)      ? NEG_INF : va;
        float vb2 = (lane + 32 == bi) ? NEG_INF : vb;
        float sv; int si;
        if (va2 >= vb2) { sv = va2; si = lane; } else { sv = vb2; si = lane + 32; }
        #pragma unroll
        for (int off = 16; off; off >>= 1) {
            float ov = __shfl_xor_sync(0xffffffffu, sv, off);
            int   oi = __shfl_xor_sync(0xffffffffu, si, off);
            if (ov > sv || (ov == sv && oi < si)) { sv = ov; si = oi; }
        }

        const float ea = __expf(va - bv);
        const float eb = __expf(vb - bv);
        float ssum = ea + eb;
        #pragma unroll
        for (int off = 16; off; off >>= 1)
            ssum += __shfl_xor_sync(0xffffffffu, ssum, off);
        const float inv = 1.0f / ssum;
        const float pa = ea * inv, pb = eb * inv;

        probs_out[(size_t)row * 64 + lane]      = pa;
        probs_out[(size_t)row * 64 + lane + 32] = pb;

        imp0 += pa; imp1 += pb;
        cnt0 += (bi == lane      ? 1.f : 0.f) + (si == lane      ? 1.f : 0.f);
        cnt1 += (bi == lane + 32 ? 1.f : 0.f) + (si == lane + 32 ? 1.f : 0.f);

        if (lane == 0) {
            const float z = bv + __logf(ssum);
            z2 += z * z;
            out[IDX_OFF + row * 2]     = (float)bi;
            out[IDX_OFF + row * 2 + 1] = (float)si;
            const float e2 = __expf(sv - bv);
            const float dn = 1.0f / (1.0f + e2);
            out[SC_OFF + row * 2]     = dn;
            out[SC_OFF + row * 2 + 1] = e2 * dn;
        }
    }

    // ---- CTA-level stats reduce in smem, then one row of g_part ----
    atomicAdd(&st[lane],      imp0);
    atomicAdd(&st[lane + 32], imp1);
    atomicAdd(&st[64 + lane], cnt0);
    atomicAdd(&st[96 + lane], cnt1);
    if (lane == 0) atomicAdd(&st[128], z2);
    __syncthreads();

    if (tid < 129) g_part[blockIdx.x][tid] = st[tid];

    // ---- last-CTA finalize (self-resetting counter) ----
    __shared__ unsigned int s_last;
    __threadfence();
    __syncthreads();
    if (tid == 0) {
        unsigned int old = atomicInc(&g_ctr, NCTA - 1);
        s_last = (old == NCTA - 1) ? 1u : 0u;
    }
    __syncthreads();
    if (s_last && tid < 129) {
        __threadfence();
        float ssum = 0.f;
        #pragma unroll 1
        for (int c = 0; c < NCTA; c++) ssum += g_part[c][tid];
        if (tid < 64)       out[IMP_OFF + tid]         = ssum * (1.0f / 16384.0f);
        else if (tid < 128) out[LOAD_OFF + (tid - 64)] = ssum * (1.0f / 32768.0f);
        else                out[Z_OFF]                 = ssum * (1.0f / 16384.0f);
    }
}

extern "C" void kernel_launch(void* const* d_in, const int* in_sizes, int n_in,
                              void* d_out, int out_size) {
    const float* x = (const float*)d_in[0];   // [4,4096,4096] f32
    const float* W = (const float*)d_in[1];   // [64,4096] f32
    float* out = (float*)d_out;
    (void)in_sizes; (void)n_in; (void)out_size;
    cudaFuncSetAttribute(router_kernel, cudaFuncAttributeMaxDynamicSharedMemorySize,
                         DSM_BYTES);
    router_kernel<<<NCTA, 256, DSM_BYTES>>>(x, W, out);
}